// round 14
// baseline (speedup 1.0000x reference)
#include <cuda_runtime.h>
#include <cuda_bf16.h>
#include <cstdint>

#define NB 512
#define NS 32
#define NH 512
#define ND 256
#define NC 128
#define KST 512           // compact storage: [hi(256)|lo(256)] per row
#define CAND_CAP 16384
#define CAND_THR 3e-5f

// ---------------- device scratch (static, no allocation) ----------------
__device__ __nv_bfloat16 g_Aext[NB * KST];                  // [b][512] = [xh|xl]
__device__ __nv_bfloat16 g_Bext[(size_t)NS * NH * KST];     // [s*512+h][512] = [wh|wl]
__device__ float g_hTop[NB * NH];                           // relu(max_s z) [b][h]
__device__ int   g_cnt[NH * NS];                            // argmax histogram
__device__ float g_muPart[16][ND];                          // meanUpd partials
__device__ float g_logPart[4][NB * NC];                     // partial logits by h-quarter
__device__ float g_lossRow[NB];
__device__ float g_corrRow[NB];
__device__ int   g_candCount;
__device__ int4  g_cand[CAND_CAP];                          // (b, h, s1, 0)

// ---------------- PTX helpers (plain sm_100 safe) ----------------
__device__ __forceinline__ uint32_t smem_u32(const void* p) {
    uint32_t a;
    asm("{ .reg .u64 t; cvta.to.shared.u64 t, %1; cvt.u32.u64 %0, t; }" : "=r"(a) : "l"(p));
    return a;
}
#define CP_ASYNC16(dst, src) \
    asm volatile("cp.async.cg.shared.global [%0], [%1], 16;" :: "r"(dst), "l"(src) : "memory")
#define CP_COMMIT() asm volatile("cp.async.commit_group;" ::: "memory")
#define CP_WAIT_GROUP(n) asm volatile("cp.async.wait_group %0;" :: "n"(n) : "memory")

__device__ __forceinline__ void ldsm4(uint32_t* r, uint32_t addr) {
    asm volatile("ldmatrix.sync.aligned.m8n8.x4.shared.b16 {%0,%1,%2,%3}, [%4];"
        : "=r"(r[0]), "=r"(r[1]), "=r"(r[2]), "=r"(r[3]) : "r"(addr));
}
__device__ __forceinline__ void mma16816(float* c, const uint32_t* a, const uint32_t* b) {
    asm volatile("mma.sync.aligned.m16n8k16.row.col.f32.bf16.bf16.f32 "
        "{%0,%1,%2,%3}, {%4,%5,%6,%7}, {%8,%9}, {%0,%1,%2,%3};"
        : "+f"(c[0]), "+f"(c[1]), "+f"(c[2]), "+f"(c[3])
        : "r"(a[0]), "r"(a[1]), "r"(a[2]), "r"(a[3]), "r"(b[0]), "r"(b[1]));
}

// swizzled 16B-slot offset inside a [rows][64B] tile (4 slots/row)
__device__ __forceinline__ uint32_t phys64(int row, int c) {
    return (uint32_t)(row * 64 + (((c ^ (row >> 1)) & 3) << 4));
}

// bf16x3 folded-K chunk source offsets (elements), K chunk = 32.
// chunks 0-7: xh*wh, 8-15: xh*wl, 16-23: xl*wh
__device__ __forceinline__ int offA_chunk(int c) {
    return (c < 16) ? (c & 7) * 32 : 256 + (c - 16) * 32;
}
__device__ __forceinline__ int offB_chunk(int c) {
    return ((c >= 8 && c < 16) ? 256 : 0) + (c & 7) * 32;
}

// ---------------- bf16 split helpers ----------------
__device__ __forceinline__ void split2(float a, float b, uint32_t& hi, uint32_t& lo) {
    __nv_bfloat16 h0 = __float2bfloat16_rn(a);
    __nv_bfloat16 h1 = __float2bfloat16_rn(b);
    __nv_bfloat16 l0 = __float2bfloat16_rn(a - __bfloat162float(h0));
    __nv_bfloat16 l1 = __float2bfloat16_rn(b - __bfloat162float(h1));
    __nv_bfloat162 hh; hh.x = h0; hh.y = h1;
    __nv_bfloat162 ll; ll.x = l0; ll.y = l1;
    hi = *(uint32_t*)&hh; lo = *(uint32_t*)&ll;
}

// ---------------- convert x -> A2 (+ meanUpd partials) ----------------
__global__ void convx_kernel(const float* __restrict__ x) {
    int idx = blockIdx.x * 256 + threadIdx.x;   // 0..32767 float4s
    float4 v = ((const float4*)x)[idx];
    int b = idx >> 6, q = idx & 63, d = q * 4;
    uint32_t hA, lA, hB, lB;
    split2(v.x, v.y, hA, lA);
    split2(v.z, v.w, hB, lB);
    uint32_t* base = (uint32_t*)(g_Aext + b * KST);
    uint2 hi2; hi2.x = hA; hi2.y = hB;
    uint2 lo2; lo2.x = lA; lo2.y = lB;
    *(uint2*)(base + (d >> 1)) = hi2;
    *(uint2*)(base + ((256 + d) >> 1)) = lo2;
    if (blockIdx.x < 16) {
        int k = blockIdx.x, dd = threadIdx.x;
        float acc = 0.f;
        #pragma unroll 8
        for (int bb = 0; bb < 32; ++bb) {
            float xv = x[(k * 32 + bb) * ND + dd];
            acc += (xv > 0.f ? 1.f : 0.f) - (xv < 0.f ? 1.f : 0.f);
        }
        g_muPart[k][dd] = acc;
    }
}

// ---------------- W0 -> B2: 2 float4s/thread (+ zero scratch piggyback) ------
__global__ void convw_kernel(const float* __restrict__ W0) {
    int bid = blockIdx.x, tid = threadIdx.x;
    if (bid < 16) {
        #pragma unroll
        for (int j = 0; j < 4; ++j) g_cnt[bid * 1024 + j * 256 + tid] = 0;
    } else if (bid == 16 && tid == 0) {
        g_candCount = 0;
    }
    #pragma unroll
    for (int half = 0; half < 2; ++half) {
        int idx = (bid * 2 + half) * 256 + tid;     // 0..1048575 float4s
        float4 v = ((const float4*)W0)[idx];
        int row = idx >> 6, q = idx & 63, d = q * 4;   // row = s*512+h
        uint32_t hA, lA, hB, lB;
        split2(v.x, v.y, hA, lA);
        split2(v.z, v.w, hB, lB);
        uint32_t* base = (uint32_t*)(g_Bext + (size_t)row * KST);
        uint2 hi2; hi2.x = hA; hi2.y = hB;
        uint2 lo2; lo2.x = lA; lo2.y = lB;
        *(uint2*)(base + (d >> 1)) = hi2;
        *(uint2*)(base + ((256 + d) >> 1)) = lo2;
    }
}

// ---------------- mma.sync GEMM + fused max/argmax epilogue ----------------
// (round-7 proven config) grid (64,4), 256 threads (8 warps: 2 wb x 4 wn),
// CTA tile 128 b x 256 n. K: 24 chunks of 32, 4-stage ring (24KB/stage, 96KB).
#define NCHUNK 24
#define STAGE_B 24576

__global__ __launch_bounds__(256, 1)
void gemm_mma_kernel(const float* __restrict__ b0) {
    extern __shared__ char sm[];
    const uint32_t sbase = smem_u32(sm);
    const int tid = threadIdx.x;
    const int lane = tid & 31, warp = tid >> 5;
    const int wb = warp >> 2, wn = warp & 3;
    const int hBase = blockIdx.x * 8;
    const int bTile = blockIdx.y * 128;

    const int prow = tid >> 2, pc = tid & 3;
    const uint32_t dA0 = phys64(prow, pc), dA1 = phys64(prow + 64, pc);
    uint32_t dB[4];
    const __nv_bfloat16* srcB[4];
    #pragma unroll
    for (int r = 0; r < 4; ++r) {
        int n = prow + 64 * r;
        dB[r] = 8192 + phys64(n, pc);
        srcB[r] = g_Bext + (size_t)((n >> 3) * NH + hBase + (n & 7)) * KST + pc * 8;
    }
    const __nv_bfloat16* srcA0 = g_Aext + (size_t)(bTile + prow) * KST + pc * 8;
    const __nv_bfloat16* srcA1 = g_Aext + (size_t)(bTile + prow + 64) * KST + pc * 8;

    uint32_t aOff[2][4], bOff[2][4];
    {
        const int arow = lane & 15, asl = lane >> 4;
        #pragma unroll
        for (int mb = 0; mb < 4; ++mb) {
            int row = wb * 64 + mb * 16 + arow;
            aOff[0][mb] = phys64(row, asl);
            aOff[1][mb] = phys64(row, 2 + asl);
        }
        const int brow = ((lane >> 4) << 3) + (lane & 7), bsl = (lane >> 3) & 1;
        #pragma unroll
        for (int jb = 0; jb < 4; ++jb) {
            int n = wn * 64 + jb * 16 + brow;
            bOff[0][jb] = 8192 + phys64(n, bsl);
            bOff[1][jb] = 8192 + phys64(n, 2 + bsl);
        }
    }

    float acc[4][8][4];
    #pragma unroll
    for (int mb = 0; mb < 4; ++mb)
        #pragma unroll
        for (int nb = 0; nb < 8; ++nb)
            #pragma unroll
            for (int q = 0; q < 4; ++q) acc[mb][nb][q] = 0.f;

    #pragma unroll
    for (int p = 0; p < 3; ++p) {
        uint32_t st = sbase + p * STAGE_B;
        const int oa = offA_chunk(p), ob = offB_chunk(p);
        CP_ASYNC16(st + dA0, srcA0 + oa);
        CP_ASYNC16(st + dA1, srcA1 + oa);
        #pragma unroll
        for (int r = 0; r < 4; ++r) CP_ASYNC16(st + dB[r], srcB[r] + ob);
        CP_COMMIT();
    }

    for (int c = 0; c < NCHUNK; ++c) {
        CP_WAIT_GROUP(2);
        __syncthreads();
        if (c + 3 < NCHUNK) {
            uint32_t st = sbase + ((c + 3) & 3) * STAGE_B;
            const int oa = offA_chunk(c + 3), ob = offB_chunk(c + 3);
            CP_ASYNC16(st + dA0, srcA0 + oa);
            CP_ASYNC16(st + dA1, srcA1 + oa);
            #pragma unroll
            for (int r = 0; r < 4; ++r) CP_ASYNC16(st + dB[r], srcB[r] + ob);
        }
        CP_COMMIT();

        const uint32_t base = sbase + (c & 3) * STAGE_B;
        uint32_t af[2][4][4], bf[2][4][4];
        #pragma unroll
        for (int kh = 0; kh < 2; ++kh) {
            #pragma unroll
            for (int mb = 0; mb < 4; ++mb) ldsm4(af[kh][mb], base + aOff[kh][mb]);
            #pragma unroll
            for (int jb = 0; jb < 4; ++jb) ldsm4(bf[kh][jb], base + bOff[kh][jb]);
        }
        #pragma unroll
        for (int kh = 0; kh < 2; ++kh)
            #pragma unroll
            for (int mb = 0; mb < 4; ++mb)
                #pragma unroll
                for (int jb = 0; jb < 4; ++jb) {
                    mma16816(acc[mb][jb * 2],     af[kh][mb], &bf[kh][jb][0]);
                    mma16816(acc[mb][jb * 2 + 1], af[kh][mb], &bf[kh][jb][2]);
                }
    }
    __syncthreads();

    // ---- epilogue phase 1: per-warp top-2 over this warp's 8 s ----
    float* v1s = (float*)sm;
    int*   s1s = (int*)(sm + 16384);
    float* v2s = (float*)(sm + 32768);

    float biasv[8][2];
    #pragma unroll
    for (int nb = 0; nb < 8; ++nb)
        #pragma unroll
        for (int q = 0; q < 2; ++q)
            biasv[nb][q] = __ldg(&b0[(wn * 8 + nb) * NH + hBase + (lane & 3) * 2 + q]);

    #pragma unroll
    for (int mb = 0; mb < 4; ++mb)
        #pragma unroll
        for (int half = 0; half < 2; ++half)
            #pragma unroll
            for (int q = 0; q < 2; ++q) {
                float m1 = -3.4e38f, m2 = -3.4e38f; int s1 = 0;
                #pragma unroll
                for (int nb = 0; nb < 8; ++nb) {
                    float v = acc[mb][nb][half * 2 + q] + biasv[nb][q];
                    if (v > m1) { m2 = m1; m1 = v; s1 = wn * 8 + nb; }
                    else if (v > m2) m2 = v;
                }
                int row = wb * 64 + mb * 16 + half * 8 + (lane >> 2);
                int hl = (lane & 3) * 2 + q;
                int e = row * 8 + hl;
                v1s[wn * 1024 + e] = m1;
                s1s[wn * 1024 + e] = s1;
                v2s[wn * 1024 + e] = m2;
            }
    __syncthreads();

    // ---- epilogue phase 2: combine, write hTop, hist, candidates ----
    {
        const int e0 = tid * 4;
        float a1v[4][4], a2v[4][4]; int a1s[4][4];
        #pragma unroll
        for (int w = 0; w < 4; ++w) {
            *(float4*)a1v[w] = *(float4*)&v1s[w * 1024 + e0];
            *(int4*)a1s[w]   = *(int4*)&s1s[w * 1024 + e0];
            *(float4*)a2v[w] = *(float4*)&v2s[w * 1024 + e0];
        }
        float relu4[4];
        const int b = bTile + (e0 >> 3);
        #pragma unroll
        for (int k = 0; k < 4; ++k) {
            float m1 = -3.4e38f, m2 = -3.4e38f; int s1 = 0;
            #pragma unroll
            for (int w = 0; w < 4; ++w) {
                float a1 = a1v[w][k], a2 = a2v[w][k];
                if (a1 > m1) { m2 = fmaxf(m1, fmaxf(m2, a2)); m1 = a1; s1 = a1s[w][k]; }
                else { m2 = fmaxf(m2, a1); }
            }
            relu4[k] = fmaxf(m1, 0.f);
            const int h = hBase + ((e0 + k) & 7);
            atomicAdd(&g_cnt[h * NS + s1], 1);
            if (m1 - m2 < CAND_THR) {
                int idx = atomicAdd(&g_candCount, 1);
                if (idx < CAND_CAP) { int4 cd; cd.x = b; cd.y = h; cd.z = s1; cd.w = 0; g_cand[idx] = cd; }
            }
        }
        *(float4*)&g_hTop[(size_t)b * NH + hBase + (e0 & 7)] = *(float4*)relu4;
    }
}

// ---------------- exact fp32 fixup of near-tie argmax decisions ----------------
__global__ void fixup_kernel(const float* __restrict__ x, const float* __restrict__ W0,
                             const float* __restrict__ b0) {
    __shared__ float part[256];
    __shared__ float zrow[NS];
    int cnt = g_candCount; if (cnt > CAND_CAP) cnt = CAND_CAP;
    const int t = threadIdx.x, s = t >> 3, p = t & 7;
    for (int i = blockIdx.x; i < cnt; i += gridDim.x) {
        int4 cd = g_cand[i];
        const float* xr = x + cd.x * ND;
        const float* wr = W0 + (size_t)s * (NH * ND) + cd.y * ND;
        float acc = 0.f;
        #pragma unroll 8
        for (int d = p * 32; d < p * 32 + 32; ++d) acc = fmaf(xr[d], wr[d], acc);
        part[t] = acc;
        __syncthreads();
        if (p == 0) {
            float z = part[t];
            #pragma unroll
            for (int j = 1; j < 8; ++j) z += part[t + j];
            zrow[s] = z + b0[s * NH + cd.y];
        }
        __syncthreads();
        if (t == 0) {
            float m = zrow[0]; int sm_ = 0;
            #pragma unroll
            for (int ss = 1; ss < NS; ++ss)
                if (zrow[ss] > m) { m = zrow[ss]; sm_ = ss; }
            if (sm_ != cd.z) {
                atomicSub(&g_cnt[cd.y * NS + cd.z], 1);
                atomicAdd(&g_cnt[cd.y * NS + sm_], 1);
            }
        }
        __syncthreads();
    }
}

// ---------------- topKweights via histogram-weighted W0 ----------------
__global__ void topkw_kernel(const float* __restrict__ W0, float* __restrict__ out) {
    const int h = blockIdx.x;
    const int d = threadIdx.x;
    __shared__ float cs[NS];
    if (d < NS) cs[d] = (float)g_cnt[h * NS + d];
    __syncthreads();
    float mu = 0.f;
    #pragma unroll
    for (int k = 0; k < 16; ++k) mu += g_muPart[k][d];
    float acc = 0.f;
    #pragma unroll
    for (int s = 0; s < NS; ++s)
        acc = fmaf(cs[s], W0[(size_t)s * (NH * ND) + h * ND + d], acc);
    out[2 + NB * NC + h * ND + d] = acc * (1.f / (float)NB) + mu * (0.001f / (float)NB);
}

// ---------------- output head part 1: partial logits over a 128-h quarter ----
// grid (64 b-groups, 4 h-quarters) x 256 threads. 8 b-rows per block.
__global__ __launch_bounds__(256)
void outpart_kernel(const float* __restrict__ W1) {
    __shared__ float sx[8][NH / 4];    // 4 KB   (this quarter's h slice)
    __shared__ float w1s[32][129];     // 16.5 KB
    const int tid = threadIdx.x;
    const int lane = tid & 31, warp = tid >> 5;
    const int bBase = blockIdx.x * 8;
    const int hq = blockIdx.y;         // h-quarter
    const int hOff = hq * (NH / 4);

    {
        int i = tid;                   // float4 idx 0..255
        int r = i >> 5, col4 = i & 31;
        ((float4*)sx)[i] = ((const float4*)(g_hTop + (size_t)(bBase + r) * NH + hOff))[col4];
    }

    const int rg = warp >> 2;          // 0/1 -> rows rg*4..rg*4+3
    const int cq = warp & 3;
    const int c = cq * 32 + lane;
    float acc[4] = {0.f, 0.f, 0.f, 0.f};

    for (int ch = 0; ch < 4; ++ch) {
        __syncthreads();
        #pragma unroll
        for (int k = 0; k < 4; ++k) {
            int i = tid + k * 256;              // float4 idx 0..1023
            int c2 = i >> 3, col4 = i & 7;
            float4 v = ((const float4*)W1)[c2 * (NH / 4) + (hOff >> 2) + ch * 8 + col4];
            w1s[col4 * 4 + 0][c2] = v.x;
            w1s[col4 * 4 + 1][c2] = v.y;
            w1s[col4 * 4 + 2][c2] = v.z;
            w1s[col4 * 4 + 3][c2] = v.w;
        }
        __syncthreads();
        #pragma unroll
        for (int j4 = 0; j4 < 8; ++j4) {
            float w0v = w1s[j4 * 4 + 0][c];
            float w1v = w1s[j4 * 4 + 1][c];
            float w2v = w1s[j4 * 4 + 2][c];
            float w3v = w1s[j4 * 4 + 3][c];
            #pragma unroll
            for (int r = 0; r < 4; ++r) {
                float4 xv = *(const float4*)&sx[rg * 4 + r][ch * 32 + j4 * 4];
                acc[r] = fmaf(xv.x, w0v, acc[r]);
                acc[r] = fmaf(xv.y, w1v, acc[r]);
                acc[r] = fmaf(xv.z, w2v, acc[r]);
                acc[r] = fmaf(xv.w, w3v, acc[r]);
            }
        }
    }
    #pragma unroll
    for (int r = 0; r < 4; ++r)
        g_logPart[hq][(size_t)(bBase + rg * 4 + r) * NC + c] = acc[r];
}

// ---------------- output head part 2: combine + log_softmax ----------------
__global__ __launch_bounds__(256)
void softmax_kernel(const float* __restrict__ b1, const int* __restrict__ y,
                    float* __restrict__ out) {
    const int lane = threadIdx.x & 31, warp = threadIdx.x >> 5;
    const int b = blockIdx.x * 8 + warp;
    float v[4];
    #pragma unroll
    for (int k = 0; k < 4; ++k) {
        const int c = lane + k * 32;
        float s = b1[c];
        #pragma unroll
        for (int p = 0; p < 4; ++p) s += g_logPart[p][(size_t)b * NC + c];
        v[k] = s;
    }
    float m = v[0]; int am = lane;
    #pragma unroll
    for (int k = 1; k < 4; ++k)
        if (v[k] > m) { m = v[k]; am = lane + k * 32; }
    #pragma unroll
    for (int off = 16; off > 0; off >>= 1) {
        float om = __shfl_xor_sync(0xffffffffu, m, off);
        int oa = __shfl_xor_sync(0xffffffffu, am, off);
        if (om > m || (om == m && oa < am)) { m = om; am = oa; }
    }
    float ssum = 0.f;
    #pragma unroll
    for (int k = 0; k < 4; ++k) ssum += expf(v[k] - m);
    #pragma unroll
    for (int off = 16; off > 0; off >>= 1)
        ssum += __shfl_xor_sync(0xffffffffu, ssum, off);
    const float lse = logf(ssum);
    #pragma unroll
    for (int k = 0; k < 4; ++k)
        out[2 + (size_t)b * NC + lane + k * 32] = v[k] - m - lse;
    const int yb = y[b];
    if (lane == (yb & 31)) g_lossRow[b] = -(v[yb >> 5] - m - lse);
    if (lane == 0) g_corrRow[b] = (am == yb) ? 1.f : 0.f;
}

__global__ void finalize_kernel(float* out) {
    __shared__ float sl[NB], sc[NB];
    int t = threadIdx.x;
    sl[t] = g_lossRow[t];
    sc[t] = g_corrRow[t];
    __syncthreads();
    for (int off = NB / 2; off > 0; off >>= 1) {
        if (t < off) { sl[t] += sl[t + off]; sc[t] += sc[t + off]; }
        __syncthreads();
    }
    if (t == 0) { out[0] = sl[0] / (float)NB; out[1] = sc[0] / (float)NB; }
}

// ---------------- launcher ----------------
extern "C" void kernel_launch(void* const* d_in, const int* in_sizes, int n_in,
                              void* d_out, int out_size) {
    const float* x  = (const float*)d_in[0];
    const int*   y  = (const int*)d_in[1];
    const float* W0 = (const float*)d_in[2];
    const float* b0 = (const float*)d_in[3];
    const float* W1 = (const float*)d_in[4];
    const float* b1 = (const float*)d_in[5];
    float* out = (float*)d_out;

    static cudaStream_t s1;
    static cudaEvent_t eF, eX, eG, eS;
    static bool inited = false;
    if (!inited) {
        cudaStreamCreateWithFlags(&s1, cudaStreamNonBlocking);
        cudaEventCreateWithFlags(&eF, cudaEventDisableTiming);
        cudaEventCreateWithFlags(&eX, cudaEventDisableTiming);
        cudaEventCreateWithFlags(&eG, cudaEventDisableTiming);
        cudaEventCreateWithFlags(&eS, cudaEventDisableTiming);
        cudaFuncSetAttribute(gemm_mma_kernel,
                             cudaFuncAttributeMaxDynamicSharedMemorySize, 4 * STAGE_B);
        inited = true;
    }

    // fork side stream into the capture first, then launch on it
    cudaEventRecord(eF, 0);
    cudaStreamWaitEvent(s1, eF, 0);
    convx_kernel<<<128, 256, 0, s1>>>(x);
    cudaEventRecord(eX, s1);

    convw_kernel<<<2048, 256>>>(W0);
    cudaStreamWaitEvent(0, eX, 0);

    gemm_mma_kernel<<<dim3(64, 4), 256, 4 * STAGE_B>>>(b0);
    cudaEventRecord(eG, 0);

    // side stream: SHORTER chain (fixup -> topkw), forked off gemm
    cudaStreamWaitEvent(s1, eG, 0);
    fixup_kernel<<<148, 256, 0, s1>>>(x, W0, b0);
    topkw_kernel<<<NH, ND, 0, s1>>>(W0, out);
    cudaEventRecord(eS, s1);

    // main stream: LONGER chain (output head) stays on the timed stream
    outpart_kernel<<<dim3(64, 4), 256>>>(W1);
    softmax_kernel<<<64, 256>>>(b1, y, out);
    finalize_kernel<<<1, NB>>>(out);
    cudaStreamWaitEvent(0, eS, 0);
}

// round 15
// speedup vs baseline: 1.1317x; 1.1317x over previous
#include <cuda_runtime.h>
#include <cuda_bf16.h>
#include <cstdint>

#define NB 512
#define NS 32
#define NH 512
#define ND 256
#define NC 128
#define KST 512           // compact storage: [hi(256)|lo(256)] per row
#define CAND_CAP 16384
#define CAND_THR 3e-5f

// ---------------- device scratch (static, no allocation) ----------------
__device__ __nv_bfloat16 g_Aext[NB * KST];                  // [b][512] = [xh|xl]
__device__ __nv_bfloat16 g_Bext[(size_t)NS * NH * KST];     // [s*512+h][512] = [wh|wl]
__device__ float g_hTop[NB * NH];                           // relu(max_s z) [b][h]
__device__ int   g_cnt[NH * NS];                            // argmax histogram
__device__ float g_muPart[16][ND];                          // meanUpd partials
__device__ float g_logPart[4][NB * NC];                     // partial logits by h-quarter
__device__ float g_lossRow[NB];
__device__ float g_corrRow[NB];
__device__ int   g_candCount;
__device__ int4  g_cand[CAND_CAP];                          // (b, h, s1, 0)

// ---------------- PTX helpers (plain sm_100 safe) ----------------
__device__ __forceinline__ uint32_t smem_u32(const void* p) {
    uint32_t a;
    asm("{ .reg .u64 t; cvta.to.shared.u64 t, %1; cvt.u32.u64 %0, t; }" : "=r"(a) : "l"(p));
    return a;
}
#define CP_ASYNC16(dst, src) \
    asm volatile("cp.async.cg.shared.global [%0], [%1], 16;" :: "r"(dst), "l"(src) : "memory")
#define CP_COMMIT() asm volatile("cp.async.commit_group;" ::: "memory")
#define CP_WAIT_GROUP(n) asm volatile("cp.async.wait_group %0;" :: "n"(n) : "memory")

__device__ __forceinline__ void ldsm4(uint32_t* r, uint32_t addr) {
    asm volatile("ldmatrix.sync.aligned.m8n8.x4.shared.b16 {%0,%1,%2,%3}, [%4];"
        : "=r"(r[0]), "=r"(r[1]), "=r"(r[2]), "=r"(r[3]) : "r"(addr));
}
__device__ __forceinline__ void mma16816(float* c, const uint32_t* a, const uint32_t* b) {
    asm volatile("mma.sync.aligned.m16n8k16.row.col.f32.bf16.bf16.f32 "
        "{%0,%1,%2,%3}, {%4,%5,%6,%7}, {%8,%9}, {%0,%1,%2,%3};"
        : "+f"(c[0]), "+f"(c[1]), "+f"(c[2]), "+f"(c[3])
        : "r"(a[0]), "r"(a[1]), "r"(a[2]), "r"(a[3]), "r"(b[0]), "r"(b[1]));
}

// swizzled 16B-slot offset inside a [rows][64B] tile (4 slots/row)
__device__ __forceinline__ uint32_t phys64(int row, int c) {
    return (uint32_t)(row * 64 + (((c ^ (row >> 1)) & 3) << 4));
}

// bf16x3 folded-K chunk source offsets (elements), K chunk = 32.
// chunks 0-7: xh*wh, 8-15: xh*wl, 16-23: xl*wh
__device__ __forceinline__ int offA_chunk(int c) {
    return (c < 16) ? (c & 7) * 32 : 256 + (c - 16) * 32;
}
__device__ __forceinline__ int offB_chunk(int c) {
    return ((c >= 8 && c < 16) ? 256 : 0) + (c & 7) * 32;
}

// ---------------- bf16 split helpers ----------------
__device__ __forceinline__ void split2(float a, float b, uint32_t& hi, uint32_t& lo) {
    __nv_bfloat16 h0 = __float2bfloat16_rn(a);
    __nv_bfloat16 h1 = __float2bfloat16_rn(b);
    __nv_bfloat16 l0 = __float2bfloat16_rn(a - __bfloat162float(h0));
    __nv_bfloat16 l1 = __float2bfloat16_rn(b - __bfloat162float(h1));
    __nv_bfloat162 hh; hh.x = h0; hh.y = h1;
    __nv_bfloat162 ll; ll.x = l0; ll.y = l1;
    hi = *(uint32_t*)&hh; lo = *(uint32_t*)&ll;
}

// ---------------- convert x -> A2 (+ meanUpd partials) ----------------
__global__ void convx_kernel(const float* __restrict__ x) {
    int idx = blockIdx.x * 256 + threadIdx.x;   // 0..32767 float4s
    float4 v = ((const float4*)x)[idx];
    int b = idx >> 6, q = idx & 63, d = q * 4;
    uint32_t hA, lA, hB, lB;
    split2(v.x, v.y, hA, lA);
    split2(v.z, v.w, hB, lB);
    uint32_t* base = (uint32_t*)(g_Aext + b * KST);
    uint2 hi2; hi2.x = hA; hi2.y = hB;
    uint2 lo2; lo2.x = lA; lo2.y = lB;
    *(uint2*)(base + (d >> 1)) = hi2;
    *(uint2*)(base + ((256 + d) >> 1)) = lo2;
    if (blockIdx.x < 16) {
        int k = blockIdx.x, dd = threadIdx.x;
        float acc = 0.f;
        #pragma unroll 8
        for (int bb = 0; bb < 32; ++bb) {
            float xv = x[(k * 32 + bb) * ND + dd];
            acc += (xv > 0.f ? 1.f : 0.f) - (xv < 0.f ? 1.f : 0.f);
        }
        g_muPart[k][dd] = acc;
    }
}

// ---------------- W0 -> B2 (+ zero scratch piggyback) ----------------
__global__ void convw_kernel(const float* __restrict__ W0) {
    int bid = blockIdx.x, tid = threadIdx.x;
    if (bid < 16) {
        #pragma unroll
        for (int j = 0; j < 4; ++j) g_cnt[bid * 1024 + j * 256 + tid] = 0;
    } else if (bid == 16 && tid == 0) {
        g_candCount = 0;
    }
    int idx = bid * 256 + tid;                  // 0..1048575 float4s
    float4 v = ((const float4*)W0)[idx];
    int row = idx >> 6, q = idx & 63, d = q * 4;   // row = s*512+h
    uint32_t hA, lA, hB, lB;
    split2(v.x, v.y, hA, lA);
    split2(v.z, v.w, hB, lB);
    uint32_t* base = (uint32_t*)(g_Bext + (size_t)row * KST);
    uint2 hi2; hi2.x = hA; hi2.y = hB;
    uint2 lo2; lo2.x = lA; lo2.y = lB;
    *(uint2*)(base + (d >> 1)) = hi2;
    *(uint2*)(base + ((256 + d) >> 1)) = lo2;
}

// ---------------- mma.sync GEMM + fused max/argmax epilogue ----------------
// grid (64 h-tiles, 4 b-tiles), 256 threads (8 warps: 2 wb x 4 wn).
// CTA tile 128 b x 256 n. K: 24 chunks of 32, 4-stage ring (24KB/stage, 96KB).
#define NCHUNK 24
#define STAGE_B 24576

__global__ __launch_bounds__(256, 1)
void gemm_mma_kernel(const float* __restrict__ b0) {
    extern __shared__ char sm[];
    const uint32_t sbase = smem_u32(sm);
    const int tid = threadIdx.x;
    const int lane = tid & 31, warp = tid >> 5;
    const int wb = warp >> 2, wn = warp & 3;
    const int hBase = blockIdx.x * 8;
    const int bTile = blockIdx.y * 128;

    const int prow = tid >> 2, pc = tid & 3;
    const uint32_t dA0 = phys64(prow, pc), dA1 = phys64(prow + 64, pc);
    uint32_t dB[4];
    const __nv_bfloat16* srcB[4];
    #pragma unroll
    for (int r = 0; r < 4; ++r) {
        int n = prow + 64 * r;
        dB[r] = 8192 + phys64(n, pc);
        srcB[r] = g_Bext + (size_t)((n >> 3) * NH + hBase + (n & 7)) * KST + pc * 8;
    }
    const __nv_bfloat16* srcA0 = g_Aext + (size_t)(bTile + prow) * KST + pc * 8;
    const __nv_bfloat16* srcA1 = g_Aext + (size_t)(bTile + prow + 64) * KST + pc * 8;

    uint32_t aOff[2][4], bOff[2][4];
    {
        const int arow = lane & 15, asl = lane >> 4;
        #pragma unroll
        for (int mb = 0; mb < 4; ++mb) {
            int row = wb * 64 + mb * 16 + arow;
            aOff[0][mb] = phys64(row, asl);
            aOff[1][mb] = phys64(row, 2 + asl);
        }
        const int brow = ((lane >> 4) << 3) + (lane & 7), bsl = (lane >> 3) & 1;
        #pragma unroll
        for (int jb = 0; jb < 4; ++jb) {
            int n = wn * 64 + jb * 16 + brow;
            bOff[0][jb] = 8192 + phys64(n, bsl);
            bOff[1][jb] = 8192 + phys64(n, 2 + bsl);
        }
    }

    float acc[4][8][4];
    #pragma unroll
    for (int mb = 0; mb < 4; ++mb)
        #pragma unroll
        for (int nb = 0; nb < 8; ++nb)
            #pragma unroll
            for (int q = 0; q < 4; ++q) acc[mb][nb][q] = 0.f;

    #pragma unroll
    for (int p = 0; p < 3; ++p) {
        uint32_t st = sbase + p * STAGE_B;
        const int oa = offA_chunk(p), ob = offB_chunk(p);
        CP_ASYNC16(st + dA0, srcA0 + oa);
        CP_ASYNC16(st + dA1, srcA1 + oa);
        #pragma unroll
        for (int r = 0; r < 4; ++r) CP_ASYNC16(st + dB[r], srcB[r] + ob);
        CP_COMMIT();
    }

    for (int c = 0; c < NCHUNK; ++c) {
        CP_WAIT_GROUP(2);
        __syncthreads();
        if (c + 3 < NCHUNK) {
            uint32_t st = sbase + ((c + 3) & 3) * STAGE_B;
            const int oa = offA_chunk(c + 3), ob = offB_chunk(c + 3);
            CP_ASYNC16(st + dA0, srcA0 + oa);
            CP_ASYNC16(st + dA1, srcA1 + oa);
            #pragma unroll
            for (int r = 0; r < 4; ++r) CP_ASYNC16(st + dB[r], srcB[r] + ob);
        }
        CP_COMMIT();

        const uint32_t base = sbase + (c & 3) * STAGE_B;
        uint32_t af[2][4][4], bf[2][4][4];
        #pragma unroll
        for (int kh = 0; kh < 2; ++kh) {
            #pragma unroll
            for (int mb = 0; mb < 4; ++mb) ldsm4(af[kh][mb], base + aOff[kh][mb]);
            #pragma unroll
            for (int jb = 0; jb < 4; ++jb) ldsm4(bf[kh][jb], base + bOff[kh][jb]);
        }
        #pragma unroll
        for (int kh = 0; kh < 2; ++kh)
            #pragma unroll
            for (int mb = 0; mb < 4; ++mb)
                #pragma unroll
                for (int jb = 0; jb < 4; ++jb) {
                    mma16816(acc[mb][jb * 2],     af[kh][mb], &bf[kh][jb][0]);
                    mma16816(acc[mb][jb * 2 + 1], af[kh][mb], &bf[kh][jb][2]);
                }
    }
    __syncthreads();

    // ---- epilogue phase 1: per-warp top-2 over this warp's 8 s ----
    float* v1s = (float*)sm;
    int*   s1s = (int*)(sm + 16384);
    float* v2s = (float*)(sm + 32768);

    float biasv[8][2];
    #pragma unroll
    for (int nb = 0; nb < 8; ++nb)
        #pragma unroll
        for (int q = 0; q < 2; ++q)
            biasv[nb][q] = __ldg(&b0[(wn * 8 + nb) * NH + hBase + (lane & 3) * 2 + q]);

    #pragma unroll
    for (int mb = 0; mb < 4; ++mb)
        #pragma unroll
        for (int half = 0; half < 2; ++half)
            #pragma unroll
            for (int q = 0; q < 2; ++q) {
                float m1 = -3.4e38f, m2 = -3.4e38f; int s1 = 0;
                #pragma unroll
                for (int nb = 0; nb < 8; ++nb) {
                    float v = acc[mb][nb][half * 2 + q] + biasv[nb][q];
                    if (v > m1) { m2 = m1; m1 = v; s1 = wn * 8 + nb; }
                    else if (v > m2) m2 = v;
                }
                int row = wb * 64 + mb * 16 + half * 8 + (lane >> 2);
                int hl = (lane & 3) * 2 + q;
                int e = row * 8 + hl;
                v1s[wn * 1024 + e] = m1;
                s1s[wn * 1024 + e] = s1;
                v2s[wn * 1024 + e] = m2;
            }
    __syncthreads();

    // ---- epilogue phase 2: combine, write hTop, hist, candidates ----
    {
        const int e0 = tid * 4;
        float a1v[4][4], a2v[4][4]; int a1s[4][4];
        #pragma unroll
        for (int w = 0; w < 4; ++w) {
            *(float4*)a1v[w] = *(float4*)&v1s[w * 1024 + e0];
            *(int4*)a1s[w]   = *(int4*)&s1s[w * 1024 + e0];
            *(float4*)a2v[w] = *(float4*)&v2s[w * 1024 + e0];
        }
        float relu4[4];
        const int b = bTile + (e0 >> 3);
        #pragma unroll
        for (int k = 0; k < 4; ++k) {
            float m1 = -3.4e38f, m2 = -3.4e38f; int s1 = 0;
            #pragma unroll
            for (int w = 0; w < 4; ++w) {
                float a1 = a1v[w][k], a2 = a2v[w][k];
                if (a1 > m1) { m2 = fmaxf(m1, fmaxf(m2, a2)); m1 = a1; s1 = a1s[w][k]; }
                else { m2 = fmaxf(m2, a1); }
            }
            relu4[k] = fmaxf(m1, 0.f);
            const int h = hBase + ((e0 + k) & 7);
            atomicAdd(&g_cnt[h * NS + s1], 1);
            if (m1 - m2 < CAND_THR) {
                int idx = atomicAdd(&g_candCount, 1);
                if (idx < CAND_CAP) { int4 cd; cd.x = b; cd.y = h; cd.z = s1; cd.w = 0; g_cand[idx] = cd; }
            }
        }
        *(float4*)&g_hTop[(size_t)b * NH + hBase + (e0 & 7)] = *(float4*)relu4;
    }
}

// ---------------- exact fp32 fixup of near-tie argmax decisions ----------------
__global__ void fixup_kernel(const float* __restrict__ x, const float* __restrict__ W0,
                             const float* __restrict__ b0) {
    __shared__ float part[256];
    __shared__ float zrow[NS];
    int cnt = g_candCount; if (cnt > CAND_CAP) cnt = CAND_CAP;
    const int t = threadIdx.x, s = t >> 3, p = t & 7;
    for (int i = blockIdx.x; i < cnt; i += gridDim.x) {
        int4 cd = g_cand[i];
        const float* xr = x + cd.x * ND;
        const float* wr = W0 + (size_t)s * (NH * ND) + cd.y * ND;
        float acc = 0.f;
        #pragma unroll 8
        for (int d = p * 32; d < p * 32 + 32; ++d) acc = fmaf(xr[d], wr[d], acc);
        part[t] = acc;
        __syncthreads();
        if (p == 0) {
            float z = part[t];
            #pragma unroll
            for (int j = 1; j < 8; ++j) z += part[t + j];
            zrow[s] = z + b0[s * NH + cd.y];
        }
        __syncthreads();
        if (t == 0) {
            float m = zrow[0]; int sm_ = 0;
            #pragma unroll
            for (int ss = 1; ss < NS; ++ss)
                if (zrow[ss] > m) { m = zrow[ss]; sm_ = ss; }
            if (sm_ != cd.z) {
                atomicSub(&g_cnt[cd.y * NS + cd.z], 1);
                atomicAdd(&g_cnt[cd.y * NS + sm_], 1);
            }
        }
        __syncthreads();
    }
}

// ---------------- topKweights via histogram-weighted W0 ----------------
__global__ void topkw_kernel(const float* __restrict__ W0, float* __restrict__ out) {
    const int h = blockIdx.x;
    const int d = threadIdx.x;
    __shared__ float cs[NS];
    if (d < NS) cs[d] = (float)g_cnt[h * NS + d];
    __syncthreads();
    float mu = 0.f;
    #pragma unroll
    for (int k = 0; k < 16; ++k) mu += g_muPart[k][d];
    float acc = 0.f;
    #pragma unroll
    for (int s = 0; s < NS; ++s)
        acc = fmaf(cs[s], W0[(size_t)s * (NH * ND) + h * ND + d], acc);
    out[2 + NB * NC + h * ND + d] = acc * (1.f / (float)NB) + mu * (0.001f / (float)NB);
}

// ---------------- output head part 1: partial logits over a 128-h quarter ----
// grid (64 b-groups, 4 h-quarters) x 256 threads. 8 b-rows per block.
__global__ __launch_bounds__(256)
void outpart_kernel(const float* __restrict__ W1) {
    __shared__ float sx[8][NH / 4];    // 4 KB   (this quarter's h slice)
    __shared__ float w1s[32][129];     // 16.5 KB
    const int tid = threadIdx.x;
    const int lane = tid & 31, warp = tid >> 5;
    const int bBase = blockIdx.x * 8;
    const int hq = blockIdx.y;         // h-quarter
    const int hOff = hq * (NH / 4);

    {
        int i = tid;                   // float4 idx 0..255
        int r = i >> 5, col4 = i & 31;
        ((float4*)sx)[i] = ((const float4*)(g_hTop + (size_t)(bBase + r) * NH + hOff))[col4];
    }

    const int rg = warp >> 2;          // 0/1 -> rows rg*4..rg*4+3
    const int cq = warp & 3;
    const int c = cq * 32 + lane;
    float acc[4] = {0.f, 0.f, 0.f, 0.f};

    for (int ch = 0; ch < 4; ++ch) {
        __syncthreads();
        #pragma unroll
        for (int k = 0; k < 4; ++k) {
            int i = tid + k * 256;              // float4 idx 0..1023
            int c2 = i >> 3, col4 = i & 7;
            float4 v = ((const float4*)W1)[c2 * (NH / 4) + (hOff >> 2) + ch * 8 + col4];
            w1s[col4 * 4 + 0][c2] = v.x;
            w1s[col4 * 4 + 1][c2] = v.y;
            w1s[col4 * 4 + 2][c2] = v.z;
            w1s[col4 * 4 + 3][c2] = v.w;
        }
        __syncthreads();
        #pragma unroll
        for (int j4 = 0; j4 < 8; ++j4) {
            float w0v = w1s[j4 * 4 + 0][c];
            float w1v = w1s[j4 * 4 + 1][c];
            float w2v = w1s[j4 * 4 + 2][c];
            float w3v = w1s[j4 * 4 + 3][c];
            #pragma unroll
            for (int r = 0; r < 4; ++r) {
                float4 xv = *(const float4*)&sx[rg * 4 + r][ch * 32 + j4 * 4];
                acc[r] = fmaf(xv.x, w0v, acc[r]);
                acc[r] = fmaf(xv.y, w1v, acc[r]);
                acc[r] = fmaf(xv.z, w2v, acc[r]);
                acc[r] = fmaf(xv.w, w3v, acc[r]);
            }
        }
    }
    #pragma unroll
    for (int r = 0; r < 4; ++r)
        g_logPart[hq][(size_t)(bBase + rg * 4 + r) * NC + c] = acc[r];
}

// ---------------- output head part 2: combine + log_softmax ----------------
__global__ __launch_bounds__(256)
void softmax_kernel(const float* __restrict__ b1, const int* __restrict__ y,
                    float* __restrict__ out) {
    const int lane = threadIdx.x & 31, warp = threadIdx.x >> 5;
    const int b = blockIdx.x * 8 + warp;
    float v[4];
    #pragma unroll
    for (int k = 0; k < 4; ++k) {
        const int c = lane + k * 32;
        float s = b1[c];
        #pragma unroll
        for (int p = 0; p < 4; ++p) s += g_logPart[p][(size_t)b * NC + c];
        v[k] = s;
    }
    float m = v[0]; int am = lane;
    #pragma unroll
    for (int k = 1; k < 4; ++k)
        if (v[k] > m) { m = v[k]; am = lane + k * 32; }
    #pragma unroll
    for (int off = 16; off > 0; off >>= 1) {
        float om = __shfl_xor_sync(0xffffffffu, m, off);
        int oa = __shfl_xor_sync(0xffffffffu, am, off);
        if (om > m || (om == m && oa < am)) { m = om; am = oa; }
    }
    float ssum = 0.f;
    #pragma unroll
    for (int k = 0; k < 4; ++k) ssum += expf(v[k] - m);
    #pragma unroll
    for (int off = 16; off > 0; off >>= 1)
        ssum += __shfl_xor_sync(0xffffffffu, ssum, off);
    const float lse = logf(ssum);
    #pragma unroll
    for (int k = 0; k < 4; ++k)
        out[2 + (size_t)b * NC + lane + k * 32] = v[k] - m - lse;
    const int yb = y[b];
    if (lane == (yb & 31)) g_lossRow[b] = -(v[yb >> 5] - m - lse);
    if (lane == 0) g_corrRow[b] = (am == yb) ? 1.f : 0.f;
}

__global__ void finalize_kernel(float* out) {
    __shared__ float sl[NB], sc[NB];
    int t = threadIdx.x;
    sl[t] = g_lossRow[t];
    sc[t] = g_corrRow[t];
    __syncthreads();
    for (int off = NB / 2; off > 0; off >>= 1) {
        if (t < off) { sl[t] += sl[t + off]; sc[t] += sc[t + off]; }
        __syncthreads();
    }
    if (t == 0) { out[0] = sl[0] / (float)NB; out[1] = sc[0] / (float)NB; }
}

// ---------------- launcher ----------------
extern "C" void kernel_launch(void* const* d_in, const int* in_sizes, int n_in,
                              void* d_out, int out_size) {
    const float* x  = (const float*)d_in[0];
    const int*   y  = (const int*)d_in[1];
    const float* W0 = (const float*)d_in[2];
    const float* b0 = (const float*)d_in[3];
    const float* W1 = (const float*)d_in[4];
    const float* b1 = (const float*)d_in[5];
    float* out = (float*)d_out;

    static cudaStream_t s1;
    static cudaEvent_t eF, eX, eG, eO;
    static bool inited = false;
    if (!inited) {
        cudaStreamCreateWithFlags(&s1, cudaStreamNonBlocking);
        cudaEventCreateWithFlags(&eF, cudaEventDisableTiming);
        cudaEventCreateWithFlags(&eX, cudaEventDisableTiming);
        cudaEventCreateWithFlags(&eG, cudaEventDisableTiming);
        cudaEventCreateWithFlags(&eO, cudaEventDisableTiming);
        cudaFuncSetAttribute(gemm_mma_kernel,
                             cudaFuncAttributeMaxDynamicSharedMemorySize, 4 * STAGE_B);
        inited = true;
    }

    // fork side stream into the capture first, then launch on it
    cudaEventRecord(eF, 0);
    cudaStreamWaitEvent(s1, eF, 0);
    convx_kernel<<<128, 256, 0, s1>>>(x);
    cudaEventRecord(eX, s1);

    convw_kernel<<<4096, 256>>>(W0);
    cudaStreamWaitEvent(0, eX, 0);

    gemm_mma_kernel<<<dim3(64, 4), 256, 4 * STAGE_B>>>(b0);
    cudaEventRecord(eG, 0);

    // side stream: output head (depends only on g_hTop)
    cudaStreamWaitEvent(s1, eG, 0);
    outpart_kernel<<<dim3(64, 4), 256, 0, s1>>>(W1);
    softmax_kernel<<<64, 256, 0, s1>>>(b1, y, out);
    finalize_kernel<<<1, NB, 0, s1>>>(out);
    cudaEventRecord(eO, s1);

    // main stream: histogram correction + topKweights
    fixup_kernel<<<64, 256>>>(x, W0, b0);
    topkw_kernel<<<NH, ND>>>(W0, out);
    cudaStreamWaitEvent(0, eO, 0);
}

// round 16
// speedup vs baseline: 1.1598x; 1.0248x over previous
#include <cuda_runtime.h>
#include <cuda_bf16.h>
#include <cstdint>

#define NB 512
#define NS 32
#define NH 512
#define ND 256
#define NC 128
#define KST 512           // compact storage: [hi(256)|lo(256)] per row
#define CAND_CAP 16384
#define CAND_THR 3e-5f

// ---------------- device scratch (static, no allocation) ----------------
__device__ __nv_bfloat16 g_Aext[NB * KST];                  // [b][512] = [xh|xl]
__device__ __nv_bfloat16 g_Bext[(size_t)NS * NH * KST];     // [s*512+h][512] = [wh|wl]
__device__ float g_hTop[NB * NH];                           // relu(max_s z) [b][h]
__device__ int   g_cnt[NH * NS];                            // argmax histogram
__device__ float g_muPart[16][ND];                          // meanUpd partials
__device__ float g_logPart[4][NB * NC];                     // partial logits by h-quarter
__device__ float g_lossRow[NB];
__device__ float g_corrRow[NB];
__device__ int   g_candCount;
__device__ int4  g_cand[CAND_CAP];                          // (b, h, s1, 0)

// ---------------- PTX helpers (plain sm_100 safe) ----------------
__device__ __forceinline__ uint32_t smem_u32(const void* p) {
    uint32_t a;
    asm("{ .reg .u64 t; cvta.to.shared.u64 t, %1; cvt.u32.u64 %0, t; }" : "=r"(a) : "l"(p));
    return a;
}
#define CP_ASYNC16(dst, src) \
    asm volatile("cp.async.cg.shared.global [%0], [%1], 16;" :: "r"(dst), "l"(src) : "memory")
#define CP_COMMIT() asm volatile("cp.async.commit_group;" ::: "memory")
#define CP_WAIT_GROUP(n) asm volatile("cp.async.wait_group %0;" :: "n"(n) : "memory")

__device__ __forceinline__ void ldsm4(uint32_t* r, uint32_t addr) {
    asm volatile("ldmatrix.sync.aligned.m8n8.x4.shared.b16 {%0,%1,%2,%3}, [%4];"
        : "=r"(r[0]), "=r"(r[1]), "=r"(r[2]), "=r"(r[3]) : "r"(addr));
}
__device__ __forceinline__ void mma16816(float* c, const uint32_t* a, const uint32_t* b) {
    asm volatile("mma.sync.aligned.m16n8k16.row.col.f32.bf16.bf16.f32 "
        "{%0,%1,%2,%3}, {%4,%5,%6,%7}, {%8,%9}, {%0,%1,%2,%3};"
        : "+f"(c[0]), "+f"(c[1]), "+f"(c[2]), "+f"(c[3])
        : "r"(a[0]), "r"(a[1]), "r"(a[2]), "r"(a[3]), "r"(b[0]), "r"(b[1]));
}

// swizzled 16B-slot offset inside a [rows][64B] tile (4 slots/row)
__device__ __forceinline__ uint32_t phys64(int row, int c) {
    return (uint32_t)(row * 64 + (((c ^ (row >> 1)) & 3) << 4));
}

// bf16x3 folded-K chunk source offsets (elements), K chunk = 32.
// chunks 0-7: xh*wh, 8-15: xh*wl, 16-23: xl*wh
__device__ __forceinline__ int offA_chunk(int c) {
    return (c < 16) ? (c & 7) * 32 : 256 + (c - 16) * 32;
}
__device__ __forceinline__ int offB_chunk(int c) {
    return ((c >= 8 && c < 16) ? 256 : 0) + (c & 7) * 32;
}

// ---------------- bf16 split helpers ----------------
__device__ __forceinline__ void split2(float a, float b, uint32_t& hi, uint32_t& lo) {
    __nv_bfloat16 h0 = __float2bfloat16_rn(a);
    __nv_bfloat16 h1 = __float2bfloat16_rn(b);
    __nv_bfloat16 l0 = __float2bfloat16_rn(a - __bfloat162float(h0));
    __nv_bfloat16 l1 = __float2bfloat16_rn(b - __bfloat162float(h1));
    __nv_bfloat162 hh; hh.x = h0; hh.y = h1;
    __nv_bfloat162 ll; ll.x = l0; ll.y = l1;
    hi = *(uint32_t*)&hh; lo = *(uint32_t*)&ll;
}

// ---------------- convert x -> A2 (+ meanUpd partials) ----------------
__global__ void convx_kernel(const float* __restrict__ x) {
    int idx = blockIdx.x * 256 + threadIdx.x;   // 0..32767 float4s
    float4 v = ((const float4*)x)[idx];
    int b = idx >> 6, q = idx & 63, d = q * 4;
    uint32_t hA, lA, hB, lB;
    split2(v.x, v.y, hA, lA);
    split2(v.z, v.w, hB, lB);
    uint32_t* base = (uint32_t*)(g_Aext + b * KST);
    uint2 hi2; hi2.x = hA; hi2.y = hB;
    uint2 lo2; lo2.x = lA; lo2.y = lB;
    *(uint2*)(base + (d >> 1)) = hi2;
    *(uint2*)(base + ((256 + d) >> 1)) = lo2;
    if (blockIdx.x < 16) {
        int k = blockIdx.x, dd = threadIdx.x;
        float acc = 0.f;
        #pragma unroll 8
        for (int bb = 0; bb < 32; ++bb) {
            float xv = x[(k * 32 + bb) * ND + dd];
            acc += (xv > 0.f ? 1.f : 0.f) - (xv < 0.f ? 1.f : 0.f);
        }
        g_muPart[k][dd] = acc;
    }
}

// ---------------- W0 -> B2 (+ zero scratch piggyback) ----------------
__global__ void convw_kernel(const float* __restrict__ W0) {
    int bid = blockIdx.x, tid = threadIdx.x;
    if (bid < 16) {
        #pragma unroll
        for (int j = 0; j < 4; ++j) g_cnt[bid * 1024 + j * 256 + tid] = 0;
    } else if (bid == 16 && tid == 0) {
        g_candCount = 0;
    }
    int idx = bid * 256 + tid;                  // 0..1048575 float4s
    float4 v = ((const float4*)W0)[idx];
    int row = idx >> 6, q = idx & 63, d = q * 4;   // row = s*512+h
    uint32_t hA, lA, hB, lB;
    split2(v.x, v.y, hA, lA);
    split2(v.z, v.w, hB, lB);
    uint32_t* base = (uint32_t*)(g_Bext + (size_t)row * KST);
    uint2 hi2; hi2.x = hA; hi2.y = hB;
    uint2 lo2; lo2.x = lA; lo2.y = lB;
    *(uint2*)(base + (d >> 1)) = hi2;
    *(uint2*)(base + ((256 + d) >> 1)) = lo2;
}

// ---------------- mma.sync GEMM + fused max/argmax epilogue ----------------
// grid (64 h-tiles, 4 b-tiles), 256 threads (8 warps: 2 wb x 4 wn).
// CTA tile 128 b x 256 n. K: 24 chunks of 32, 4-stage ring (24KB/stage, 96KB).
#define NCHUNK 24
#define STAGE_B 24576

__global__ __launch_bounds__(256, 1)
void gemm_mma_kernel(const float* __restrict__ b0) {
    extern __shared__ char sm[];
    const uint32_t sbase = smem_u32(sm);
    const int tid = threadIdx.x;
    const int lane = tid & 31, warp = tid >> 5;
    const int wb = warp >> 2, wn = warp & 3;
    const int hBase = blockIdx.x * 8;
    const int bTile = blockIdx.y * 128;

    const int prow = tid >> 2, pc = tid & 3;
    const uint32_t dA0 = phys64(prow, pc), dA1 = phys64(prow + 64, pc);
    uint32_t dB[4];
    const __nv_bfloat16* srcB[4];
    #pragma unroll
    for (int r = 0; r < 4; ++r) {
        int n = prow + 64 * r;
        dB[r] = 8192 + phys64(n, pc);
        srcB[r] = g_Bext + (size_t)((n >> 3) * NH + hBase + (n & 7)) * KST + pc * 8;
    }
    const __nv_bfloat16* srcA0 = g_Aext + (size_t)(bTile + prow) * KST + pc * 8;
    const __nv_bfloat16* srcA1 = g_Aext + (size_t)(bTile + prow + 64) * KST + pc * 8;

    uint32_t aOff[2][4], bOff[2][4];
    {
        const int arow = lane & 15, asl = lane >> 4;
        #pragma unroll
        for (int mb = 0; mb < 4; ++mb) {
            int row = wb * 64 + mb * 16 + arow;
            aOff[0][mb] = phys64(row, asl);
            aOff[1][mb] = phys64(row, 2 + asl);
        }
        const int brow = ((lane >> 4) << 3) + (lane & 7), bsl = (lane >> 3) & 1;
        #pragma unroll
        for (int jb = 0; jb < 4; ++jb) {
            int n = wn * 64 + jb * 16 + brow;
            bOff[0][jb] = 8192 + phys64(n, bsl);
            bOff[1][jb] = 8192 + phys64(n, 2 + bsl);
        }
    }

    float acc[4][8][4];
    #pragma unroll
    for (int mb = 0; mb < 4; ++mb)
        #pragma unroll
        for (int nb = 0; nb < 8; ++nb)
            #pragma unroll
            for (int q = 0; q < 4; ++q) acc[mb][nb][q] = 0.f;

    #pragma unroll
    for (int p = 0; p < 3; ++p) {
        uint32_t st = sbase + p * STAGE_B;
        const int oa = offA_chunk(p), ob = offB_chunk(p);
        CP_ASYNC16(st + dA0, srcA0 + oa);
        CP_ASYNC16(st + dA1, srcA1 + oa);
        #pragma unroll
        for (int r = 0; r < 4; ++r) CP_ASYNC16(st + dB[r], srcB[r] + ob);
        CP_COMMIT();
    }

    for (int c = 0; c < NCHUNK; ++c) {
        CP_WAIT_GROUP(2);
        __syncthreads();
        if (c + 3 < NCHUNK) {
            uint32_t st = sbase + ((c + 3) & 3) * STAGE_B;
            const int oa = offA_chunk(c + 3), ob = offB_chunk(c + 3);
            CP_ASYNC16(st + dA0, srcA0 + oa);
            CP_ASYNC16(st + dA1, srcA1 + oa);
            #pragma unroll
            for (int r = 0; r < 4; ++r) CP_ASYNC16(st + dB[r], srcB[r] + ob);
        }
        CP_COMMIT();

        const uint32_t base = sbase + (c & 3) * STAGE_B;
        uint32_t af[2][4][4], bf[2][4][4];
        #pragma unroll
        for (int kh = 0; kh < 2; ++kh) {
            #pragma unroll
            for (int mb = 0; mb < 4; ++mb) ldsm4(af[kh][mb], base + aOff[kh][mb]);
            #pragma unroll
            for (int jb = 0; jb < 4; ++jb) ldsm4(bf[kh][jb], base + bOff[kh][jb]);
        }
        #pragma unroll
        for (int kh = 0; kh < 2; ++kh)
            #pragma unroll
            for (int mb = 0; mb < 4; ++mb)
                #pragma unroll
                for (int jb = 0; jb < 4; ++jb) {
                    mma16816(acc[mb][jb * 2],     af[kh][mb], &bf[kh][jb][0]);
                    mma16816(acc[mb][jb * 2 + 1], af[kh][mb], &bf[kh][jb][2]);
                }
    }
    __syncthreads();

    // ---- epilogue phase 1: per-warp top-2 over this warp's 8 s ----
    float* v1s = (float*)sm;
    int*   s1s = (int*)(sm + 16384);
    float* v2s = (float*)(sm + 32768);

    float biasv[8][2];
    #pragma unroll
    for (int nb = 0; nb < 8; ++nb)
        #pragma unroll
        for (int q = 0; q < 2; ++q)
            biasv[nb][q] = __ldg(&b0[(wn * 8 + nb) * NH + hBase + (lane & 3) * 2 + q]);

    #pragma unroll
    for (int mb = 0; mb < 4; ++mb)
        #pragma unroll
        for (int half = 0; half < 2; ++half)
            #pragma unroll
            for (int q = 0; q < 2; ++q) {
                float m1 = -3.4e38f, m2 = -3.4e38f; int s1 = 0;
                #pragma unroll
                for (int nb = 0; nb < 8; ++nb) {
                    float v = acc[mb][nb][half * 2 + q] + biasv[nb][q];
                    if (v > m1) { m2 = m1; m1 = v; s1 = wn * 8 + nb; }
                    else if (v > m2) m2 = v;
                }
                int row = wb * 64 + mb * 16 + half * 8 + (lane >> 2);
                int hl = (lane & 3) * 2 + q;
                int e = row * 8 + hl;
                v1s[wn * 1024 + e] = m1;
                s1s[wn * 1024 + e] = s1;
                v2s[wn * 1024 + e] = m2;
            }
    __syncthreads();

    // ---- epilogue phase 2: combine, write hTop, hist, candidates ----
    {
        const int e0 = tid * 4;
        float a1v[4][4], a2v[4][4]; int a1s[4][4];
        #pragma unroll
        for (int w = 0; w < 4; ++w) {
            *(float4*)a1v[w] = *(float4*)&v1s[w * 1024 + e0];
            *(int4*)a1s[w]   = *(int4*)&s1s[w * 1024 + e0];
            *(float4*)a2v[w] = *(float4*)&v2s[w * 1024 + e0];
        }
        float relu4[4];
        const int b = bTile + (e0 >> 3);
        #pragma unroll
        for (int k = 0; k < 4; ++k) {
            float m1 = -3.4e38f, m2 = -3.4e38f; int s1 = 0;
            #pragma unroll
            for (int w = 0; w < 4; ++w) {
                float a1 = a1v[w][k], a2 = a2v[w][k];
                if (a1 > m1) { m2 = fmaxf(m1, fmaxf(m2, a2)); m1 = a1; s1 = a1s[w][k]; }
                else { m2 = fmaxf(m2, a1); }
            }
            relu4[k] = fmaxf(m1, 0.f);
            const int h = hBase + ((e0 + k) & 7);
            atomicAdd(&g_cnt[h * NS + s1], 1);
            if (m1 - m2 < CAND_THR) {
                int idx = atomicAdd(&g_candCount, 1);
                if (idx < CAND_CAP) { int4 cd; cd.x = b; cd.y = h; cd.z = s1; cd.w = 0; g_cand[idx] = cd; }
            }
        }
        *(float4*)&g_hTop[(size_t)b * NH + hBase + (e0 & 7)] = *(float4*)relu4;
    }
}

// ---------------- exact fp32 fixup of near-tie argmax decisions ----------------
// 256 threads = 32 s x 8 partials. Warp-shuffle reductions, 1 block barrier/iter.
__global__ void fixup_kernel(const float* __restrict__ x, const float* __restrict__ W0,
                             const float* __restrict__ b0) {
    __shared__ float zrow[NS];
    int cnt = g_candCount; if (cnt > CAND_CAP) cnt = CAND_CAP;
    const int t = threadIdx.x, s = t >> 3, p = t & 7;
    const int lane = t & 31;
    for (int i = blockIdx.x; i < cnt; i += gridDim.x) {
        int4 cd = g_cand[i];
        const float* xr = x + cd.x * ND;
        const float* wr = W0 + (size_t)s * (NH * ND) + cd.y * ND;
        float acc = 0.f;
        #pragma unroll 8
        for (int d = p * 32; d < p * 32 + 32; ++d) acc = fmaf(xr[d], wr[d], acc);
        // deterministic in-warp 8->1 sum for each s (p ascending: j=4,2,1 halving
        // would reorder; use explicit serial order via shuffles from lane p=0's view)
        // gather partials p=1..7 into p=0 in fixed ascending order:
        float sum = acc;
        #pragma unroll
        for (int j = 1; j < 8; ++j) {
            float o = __shfl_sync(0xffffffffu, acc, (lane & 24) + j, 32);
            if (p == 0) sum += o;
        }
        if (p == 0) zrow[s] = sum + b0[s * NH + cd.y];
        __syncthreads();
        if (t < 32) {
            // warp 0: serial-order argmax over 32 s (each lane holds zrow[lane])
            float zv = zrow[t];
            float m = __shfl_sync(0xffffffffu, zv, 0);
            int sm_ = 0;
            #pragma unroll
            for (int ss = 1; ss < NS; ++ss) {
                float o = __shfl_sync(0xffffffffu, zv, ss);
                if (o > m) { m = o; sm_ = ss; }
            }
            if (t == 0 && sm_ != cd.z) {
                atomicSub(&g_cnt[cd.y * NS + cd.z], 1);
                atomicAdd(&g_cnt[cd.y * NS + sm_], 1);
            }
        }
        __syncthreads();
    }
}

// ---------------- topKweights via histogram-weighted W0 ----------------
__global__ void topkw_kernel(const float* __restrict__ W0, float* __restrict__ out) {
    const int h = blockIdx.x;
    const int d = threadIdx.x;
    __shared__ float cs[NS];
    if (d < NS) cs[d] = (float)g_cnt[h * NS + d];
    __syncthreads();
    float mu = 0.f;
    #pragma unroll
    for (int k = 0; k < 16; ++k) mu += g_muPart[k][d];
    float acc = 0.f;
    #pragma unroll
    for (int s = 0; s < NS; ++s)
        acc = fmaf(cs[s], W0[(size_t)s * (NH * ND) + h * ND + d], acc);
    out[2 + NB * NC + h * ND + d] = acc * (1.f / (float)NB) + mu * (0.001f / (float)NB);
}

// ---------------- output head part 1: partial logits over a 128-h quarter ----
// grid (64 b-groups, 4 h-quarters) x 256 threads. 8 b-rows per block.
__global__ __launch_bounds__(256)
void outpart_kernel(const float* __restrict__ W1) {
    __shared__ float sx[8][NH / 4];    // 4 KB   (this quarter's h slice)
    __shared__ float w1s[32][129];     // 16.5 KB
    const int tid = threadIdx.x;
    const int lane = tid & 31, warp = tid >> 5;
    const int bBase = blockIdx.x * 8;
    const int hq = blockIdx.y;         // h-quarter
    const int hOff = hq * (NH / 4);

    {
        int i = tid;                   // float4 idx 0..255
        int r = i >> 5, col4 = i & 31;
        ((float4*)sx)[i] = ((const float4*)(g_hTop + (size_t)(bBase + r) * NH + hOff))[col4];
    }

    const int rg = warp >> 2;          // 0/1 -> rows rg*4..rg*4+3
    const int cq = warp & 3;
    const int c = cq * 32 + lane;
    float acc[4] = {0.f, 0.f, 0.f, 0.f};

    for (int ch = 0; ch < 4; ++ch) {
        __syncthreads();
        #pragma unroll
        for (int k = 0; k < 4; ++k) {
            int i = tid + k * 256;              // float4 idx 0..1023
            int c2 = i >> 3, col4 = i & 7;
            float4 v = ((const float4*)W1)[c2 * (NH / 4) + (hOff >> 2) + ch * 8 + col4];
            w1s[col4 * 4 + 0][c2] = v.x;
            w1s[col4 * 4 + 1][c2] = v.y;
            w1s[col4 * 4 + 2][c2] = v.z;
            w1s[col4 * 4 + 3][c2] = v.w;
        }
        __syncthreads();
        #pragma unroll
        for (int j4 = 0; j4 < 8; ++j4) {
            float w0v = w1s[j4 * 4 + 0][c];
            float w1v = w1s[j4 * 4 + 1][c];
            float w2v = w1s[j4 * 4 + 2][c];
            float w3v = w1s[j4 * 4 + 3][c];
            #pragma unroll
            for (int r = 0; r < 4; ++r) {
                float4 xv = *(const float4*)&sx[rg * 4 + r][ch * 32 + j4 * 4];
                acc[r] = fmaf(xv.x, w0v, acc[r]);
                acc[r] = fmaf(xv.y, w1v, acc[r]);
                acc[r] = fmaf(xv.z, w2v, acc[r]);
                acc[r] = fmaf(xv.w, w3v, acc[r]);
            }
        }
    }
    #pragma unroll
    for (int r = 0; r < 4; ++r)
        g_logPart[hq][(size_t)(bBase + rg * 4 + r) * NC + c] = acc[r];
}

// ---------------- output head part 2: combine + log_softmax ----------------
__global__ __launch_bounds__(256)
void softmax_kernel(const float* __restrict__ b1, const int* __restrict__ y,
                    float* __restrict__ out) {
    const int lane = threadIdx.x & 31, warp = threadIdx.x >> 5;
    const int b = blockIdx.x * 8 + warp;
    float v[4];
    #pragma unroll
    for (int k = 0; k < 4; ++k) {
        const int c = lane + k * 32;
        float s = b1[c];
        #pragma unroll
        for (int p = 0; p < 4; ++p) s += g_logPart[p][(size_t)b * NC + c];
        v[k] = s;
    }
    float m = v[0]; int am = lane;
    #pragma unroll
    for (int k = 1; k < 4; ++k)
        if (v[k] > m) { m = v[k]; am = lane + k * 32; }
    #pragma unroll
    for (int off = 16; off > 0; off >>= 1) {
        float om = __shfl_xor_sync(0xffffffffu, m, off);
        int oa = __shfl_xor_sync(0xffffffffu, am, off);
        if (om > m || (om == m && oa < am)) { m = om; am = oa; }
    }
    float ssum = 0.f;
    #pragma unroll
    for (int k = 0; k < 4; ++k) ssum += expf(v[k] - m);
    #pragma unroll
    for (int off = 16; off > 0; off >>= 1)
        ssum += __shfl_xor_sync(0xffffffffu, ssum, off);
    const float lse = logf(ssum);
    #pragma unroll
    for (int k = 0; k < 4; ++k)
        out[2 + (size_t)b * NC + lane + k * 32] = v[k] - m - lse;
    const int yb = y[b];
    if (lane == (yb & 31)) g_lossRow[b] = -(v[yb >> 5] - m - lse);
    if (lane == 0) g_corrRow[b] = (am == yb) ? 1.f : 0.f;
}

__global__ void finalize_kernel(float* out) {
    __shared__ float sl[NB], sc[NB];
    int t = threadIdx.x;
    sl[t] = g_lossRow[t];
    sc[t] = g_corrRow[t];
    __syncthreads();
    for (int off = NB / 2; off > 0; off >>= 1) {
        if (t < off) { sl[t] += sl[t + off]; sc[t] += sc[t + off]; }
        __syncthreads();
    }
    if (t == 0) { out[0] = sl[0] / (float)NB; out[1] = sc[0] / (float)NB; }
}

// ---------------- launcher ----------------
extern "C" void kernel_launch(void* const* d_in, const int* in_sizes, int n_in,
                              void* d_out, int out_size) {
    const float* x  = (const float*)d_in[0];
    const int*   y  = (const int*)d_in[1];
    const float* W0 = (const float*)d_in[2];
    const float* b0 = (const float*)d_in[3];
    const float* W1 = (const float*)d_in[4];
    const float* b1 = (const float*)d_in[5];
    float* out = (float*)d_out;

    static cudaStream_t s1;
    static cudaEvent_t eF, eX, eG, eO;
    static bool inited = false;
    if (!inited) {
        cudaStreamCreateWithFlags(&s1, cudaStreamNonBlocking);
        cudaEventCreateWithFlags(&eF, cudaEventDisableTiming);
        cudaEventCreateWithFlags(&eX, cudaEventDisableTiming);
        cudaEventCreateWithFlags(&eG, cudaEventDisableTiming);
        cudaEventCreateWithFlags(&eO, cudaEventDisableTiming);
        cudaFuncSetAttribute(gemm_mma_kernel,
                             cudaFuncAttributeMaxDynamicSharedMemorySize, 4 * STAGE_B);
        inited = true;
    }

    // fork side stream into the capture first, then launch on it
    cudaEventRecord(eF, 0);
    cudaStreamWaitEvent(s1, eF, 0);
    convx_kernel<<<128, 256, 0, s1>>>(x);
    cudaEventRecord(eX, s1);

    convw_kernel<<<4096, 256>>>(W0);
    cudaStreamWaitEvent(0, eX, 0);

    gemm_mma_kernel<<<dim3(64, 4), 256, 4 * STAGE_B>>>(b0);
    cudaEventRecord(eG, 0);

    // side stream: output head (depends only on g_hTop)
    cudaStreamWaitEvent(s1, eG, 0);
    outpart_kernel<<<dim3(64, 4), 256, 0, s1>>>(W1);
    softmax_kernel<<<64, 256, 0, s1>>>(b1, y, out);
    finalize_kernel<<<1, NB, 0, s1>>>(out);
    cudaEventRecord(eO, s1);

    // main stream: histogram correction + topKweights
    fixup_kernel<<<132, 256>>>(x, W0, b0);
    topkw_kernel<<<NH, ND>>>(W0, out);
    cudaStreamWaitEvent(0, eO, 0);
}

// round 17
// speedup vs baseline: 1.1622x; 1.0021x over previous
#include <cuda_runtime.h>
#include <cuda_bf16.h>
#include <cstdint>

#define NB 512
#define NS 32
#define NH 512
#define ND 256
#define NC 128
#define KST 512           // compact storage: [hi(256)|lo(256)] per row
#define CAND_CAP 16384
#define CAND_THR 3e-5f

// ---------------- device scratch (static, no allocation) ----------------
__device__ __nv_bfloat16 g_Aext[NB * KST];                  // [b][512] = [xh|xl]
__device__ __nv_bfloat16 g_Bext[(size_t)NS * NH * KST];     // [s*512+h][512] = [wh|wl]
__device__ float g_hTop[NB * NH];                           // relu(max_s z) [b][h]
__device__ int   g_cnt[NH * NS];                            // argmax histogram
__device__ float g_muPart[16][ND];                          // meanUpd partials
__device__ float g_logPart[4][NB * NC];                     // partial logits by h-quarter
__device__ float g_lossRow[NB];
__device__ float g_corrRow[NB];
__device__ int   g_candCount;
__device__ int4  g_cand[CAND_CAP];                          // (b, h, s1, 0)

// ---------------- PTX helpers (plain sm_100 safe) ----------------
__device__ __forceinline__ uint32_t smem_u32(const void* p) {
    uint32_t a;
    asm("{ .reg .u64 t; cvta.to.shared.u64 t, %1; cvt.u32.u64 %0, t; }" : "=r"(a) : "l"(p));
    return a;
}
#define CP_ASYNC16(dst, src) \
    asm volatile("cp.async.cg.shared.global [%0], [%1], 16;" :: "r"(dst), "l"(src) : "memory")
#define CP_COMMIT() asm volatile("cp.async.commit_group;" ::: "memory")
#define CP_WAIT_GROUP(n) asm volatile("cp.async.wait_group %0;" :: "n"(n) : "memory")

__device__ __forceinline__ void ldsm4(uint32_t* r, uint32_t addr) {
    asm volatile("ldmatrix.sync.aligned.m8n8.x4.shared.b16 {%0,%1,%2,%3}, [%4];"
        : "=r"(r[0]), "=r"(r[1]), "=r"(r[2]), "=r"(r[3]) : "r"(addr));
}
__device__ __forceinline__ void mma16816(float* c, const uint32_t* a, const uint32_t* b) {
    asm volatile("mma.sync.aligned.m16n8k16.row.col.f32.bf16.bf16.f32 "
        "{%0,%1,%2,%3}, {%4,%5,%6,%7}, {%8,%9}, {%0,%1,%2,%3};"
        : "+f"(c[0]), "+f"(c[1]), "+f"(c[2]), "+f"(c[3])
        : "r"(a[0]), "r"(a[1]), "r"(a[2]), "r"(a[3]), "r"(b[0]), "r"(b[1]));
}

// swizzled 16B-slot offset inside a [rows][64B] tile (4 slots/row)
__device__ __forceinline__ uint32_t phys64(int row, int c) {
    return (uint32_t)(row * 64 + (((c ^ (row >> 1)) & 3) << 4));
}

// bf16x3 folded-K chunk source offsets (elements), K chunk = 32.
// chunks 0-7: xh*wh, 8-15: xh*wl, 16-23: xl*wh
__device__ __forceinline__ int offA_chunk(int c) {
    return (c < 16) ? (c & 7) * 32 : 256 + (c - 16) * 32;
}
__device__ __forceinline__ int offB_chunk(int c) {
    return ((c >= 8 && c < 16) ? 256 : 0) + (c & 7) * 32;
}

// ---------------- bf16 split helpers ----------------
__device__ __forceinline__ void split2(float a, float b, uint32_t& hi, uint32_t& lo) {
    __nv_bfloat16 h0 = __float2bfloat16_rn(a);
    __nv_bfloat16 h1 = __float2bfloat16_rn(b);
    __nv_bfloat16 l0 = __float2bfloat16_rn(a - __bfloat162float(h0));
    __nv_bfloat16 l1 = __float2bfloat16_rn(b - __bfloat162float(h1));
    __nv_bfloat162 hh; hh.x = h0; hh.y = h1;
    __nv_bfloat162 ll; ll.x = l0; ll.y = l1;
    hi = *(uint32_t*)&hh; lo = *(uint32_t*)&ll;
}

// ---------------- convert x -> A2 (+ meanUpd partials) ----------------
__global__ void convx_kernel(const float* __restrict__ x) {
    int idx = blockIdx.x * 256 + threadIdx.x;   // 0..32767 float4s
    float4 v = ((const float4*)x)[idx];
    int b = idx >> 6, q = idx & 63, d = q * 4;
    uint32_t hA, lA, hB, lB;
    split2(v.x, v.y, hA, lA);
    split2(v.z, v.w, hB, lB);
    uint32_t* base = (uint32_t*)(g_Aext + b * KST);
    uint2 hi2; hi2.x = hA; hi2.y = hB;
    uint2 lo2; lo2.x = lA; lo2.y = lB;
    *(uint2*)(base + (d >> 1)) = hi2;
    *(uint2*)(base + ((256 + d) >> 1)) = lo2;
    if (blockIdx.x < 16) {
        int k = blockIdx.x, dd = threadIdx.x;
        float acc = 0.f;
        #pragma unroll 8
        for (int bb = 0; bb < 32; ++bb) {
            float xv = x[(k * 32 + bb) * ND + dd];
            acc += (xv > 0.f ? 1.f : 0.f) - (xv < 0.f ? 1.f : 0.f);
        }
        g_muPart[k][dd] = acc;
    }
}

// ---------------- W0 -> B2 (+ zero scratch piggyback) ----------------
__global__ void convw_kernel(const float* __restrict__ W0) {
    int bid = blockIdx.x, tid = threadIdx.x;
    if (bid < 16) {
        #pragma unroll
        for (int j = 0; j < 4; ++j) g_cnt[bid * 1024 + j * 256 + tid] = 0;
    } else if (bid == 16 && tid == 0) {
        g_candCount = 0;
    }
    int idx = bid * 256 + tid;                  // 0..1048575 float4s
    float4 v = ((const float4*)W0)[idx];
    int row = idx >> 6, q = idx & 63, d = q * 4;   // row = s*512+h
    uint32_t hA, lA, hB, lB;
    split2(v.x, v.y, hA, lA);
    split2(v.z, v.w, hB, lB);
    uint32_t* base = (uint32_t*)(g_Bext + (size_t)row * KST);
    uint2 hi2; hi2.x = hA; hi2.y = hB;
    uint2 lo2; lo2.x = lA; lo2.y = lB;
    *(uint2*)(base + (d >> 1)) = hi2;
    *(uint2*)(base + ((256 + d) >> 1)) = lo2;
}

// ---------------- mma.sync GEMM + fused max/argmax epilogue ----------------
// grid (64 h-tiles, 4 b-tiles), 256 threads (8 warps: 2 wb x 4 wn).
// CTA tile 128 b x 256 n. K: 24 chunks of 32, 4-stage ring (24KB/stage, 96KB).
#define NCHUNK 24
#define STAGE_B 24576

__global__ __launch_bounds__(256, 1)
void gemm_mma_kernel(const float* __restrict__ b0) {
    extern __shared__ char sm[];
    const uint32_t sbase = smem_u32(sm);
    const int tid = threadIdx.x;
    const int lane = tid & 31, warp = tid >> 5;
    const int wb = warp >> 2, wn = warp & 3;
    const int hBase = blockIdx.x * 8;
    const int bTile = blockIdx.y * 128;

    const int prow = tid >> 2, pc = tid & 3;
    const uint32_t dA0 = phys64(prow, pc), dA1 = phys64(prow + 64, pc);
    uint32_t dB[4];
    const __nv_bfloat16* srcB[4];
    #pragma unroll
    for (int r = 0; r < 4; ++r) {
        int n = prow + 64 * r;
        dB[r] = 8192 + phys64(n, pc);
        srcB[r] = g_Bext + (size_t)((n >> 3) * NH + hBase + (n & 7)) * KST + pc * 8;
    }
    const __nv_bfloat16* srcA0 = g_Aext + (size_t)(bTile + prow) * KST + pc * 8;
    const __nv_bfloat16* srcA1 = g_Aext + (size_t)(bTile + prow + 64) * KST + pc * 8;

    uint32_t aOff[2][4], bOff[2][4];
    {
        const int arow = lane & 15, asl = lane >> 4;
        #pragma unroll
        for (int mb = 0; mb < 4; ++mb) {
            int row = wb * 64 + mb * 16 + arow;
            aOff[0][mb] = phys64(row, asl);
            aOff[1][mb] = phys64(row, 2 + asl);
        }
        const int brow = ((lane >> 4) << 3) + (lane & 7), bsl = (lane >> 3) & 1;
        #pragma unroll
        for (int jb = 0; jb < 4; ++jb) {
            int n = wn * 64 + jb * 16 + brow;
            bOff[0][jb] = 8192 + phys64(n, bsl);
            bOff[1][jb] = 8192 + phys64(n, 2 + bsl);
        }
    }

    float acc[4][8][4];
    #pragma unroll
    for (int mb = 0; mb < 4; ++mb)
        #pragma unroll
        for (int nb = 0; nb < 8; ++nb)
            #pragma unroll
            for (int q = 0; q < 4; ++q) acc[mb][nb][q] = 0.f;

    #pragma unroll
    for (int p = 0; p < 3; ++p) {
        uint32_t st = sbase + p * STAGE_B;
        const int oa = offA_chunk(p), ob = offB_chunk(p);
        CP_ASYNC16(st + dA0, srcA0 + oa);
        CP_ASYNC16(st + dA1, srcA1 + oa);
        #pragma unroll
        for (int r = 0; r < 4; ++r) CP_ASYNC16(st + dB[r], srcB[r] + ob);
        CP_COMMIT();
    }

    for (int c = 0; c < NCHUNK; ++c) {
        CP_WAIT_GROUP(2);
        __syncthreads();
        if (c + 3 < NCHUNK) {
            uint32_t st = sbase + ((c + 3) & 3) * STAGE_B;
            const int oa = offA_chunk(c + 3), ob = offB_chunk(c + 3);
            CP_ASYNC16(st + dA0, srcA0 + oa);
            CP_ASYNC16(st + dA1, srcA1 + oa);
            #pragma unroll
            for (int r = 0; r < 4; ++r) CP_ASYNC16(st + dB[r], srcB[r] + ob);
        }
        CP_COMMIT();

        const uint32_t base = sbase + (c & 3) * STAGE_B;
        uint32_t af[2][4][4], bf[2][4][4];
        #pragma unroll
        for (int kh = 0; kh < 2; ++kh) {
            #pragma unroll
            for (int mb = 0; mb < 4; ++mb) ldsm4(af[kh][mb], base + aOff[kh][mb]);
            #pragma unroll
            for (int jb = 0; jb < 4; ++jb) ldsm4(bf[kh][jb], base + bOff[kh][jb]);
        }
        #pragma unroll
        for (int kh = 0; kh < 2; ++kh)
            #pragma unroll
            for (int mb = 0; mb < 4; ++mb)
                #pragma unroll
                for (int jb = 0; jb < 4; ++jb) {
                    mma16816(acc[mb][jb * 2],     af[kh][mb], &bf[kh][jb][0]);
                    mma16816(acc[mb][jb * 2 + 1], af[kh][mb], &bf[kh][jb][2]);
                }
    }
    __syncthreads();

    // ---- epilogue phase 1: per-warp top-2 over this warp's 8 s ----
    float* v1s = (float*)sm;
    int*   s1s = (int*)(sm + 16384);
    float* v2s = (float*)(sm + 32768);

    float biasv[8][2];
    #pragma unroll
    for (int nb = 0; nb < 8; ++nb)
        #pragma unroll
        for (int q = 0; q < 2; ++q)
            biasv[nb][q] = __ldg(&b0[(wn * 8 + nb) * NH + hBase + (lane & 3) * 2 + q]);

    #pragma unroll
    for (int mb = 0; mb < 4; ++mb)
        #pragma unroll
        for (int half = 0; half < 2; ++half)
            #pragma unroll
            for (int q = 0; q < 2; ++q) {
                float m1 = -3.4e38f, m2 = -3.4e38f; int s1 = 0;
                #pragma unroll
                for (int nb = 0; nb < 8; ++nb) {
                    float v = acc[mb][nb][half * 2 + q] + biasv[nb][q];
                    if (v > m1) { m2 = m1; m1 = v; s1 = wn * 8 + nb; }
                    else if (v > m2) m2 = v;
                }
                int row = wb * 64 + mb * 16 + half * 8 + (lane >> 2);
                int hl = (lane & 3) * 2 + q;
                int e = row * 8 + hl;
                v1s[wn * 1024 + e] = m1;
                s1s[wn * 1024 + e] = s1;
                v2s[wn * 1024 + e] = m2;
            }
    __syncthreads();

    // ---- epilogue phase 2: combine, write hTop, hist, candidates ----
    {
        const int e0 = tid * 4;
        float a1v[4][4], a2v[4][4]; int a1s[4][4];
        #pragma unroll
        for (int w = 0; w < 4; ++w) {
            *(float4*)a1v[w] = *(float4*)&v1s[w * 1024 + e0];
            *(int4*)a1s[w]   = *(int4*)&s1s[w * 1024 + e0];
            *(float4*)a2v[w] = *(float4*)&v2s[w * 1024 + e0];
        }
        float relu4[4];
        const int b = bTile + (e0 >> 3);
        #pragma unroll
        for (int k = 0; k < 4; ++k) {
            float m1 = -3.4e38f, m2 = -3.4e38f; int s1 = 0;
            #pragma unroll
            for (int w = 0; w < 4; ++w) {
                float a1 = a1v[w][k], a2 = a2v[w][k];
                if (a1 > m1) { m2 = fmaxf(m1, fmaxf(m2, a2)); m1 = a1; s1 = a1s[w][k]; }
                else { m2 = fmaxf(m2, a1); }
            }
            relu4[k] = fmaxf(m1, 0.f);
            const int h = hBase + ((e0 + k) & 7);
            atomicAdd(&g_cnt[h * NS + s1], 1);
            if (m1 - m2 < CAND_THR) {
                int idx = atomicAdd(&g_candCount, 1);
                if (idx < CAND_CAP) { int4 cd; cd.x = b; cd.y = h; cd.z = s1; cd.w = 0; g_cand[idx] = cd; }
            }
        }
        *(float4*)&g_hTop[(size_t)b * NH + hBase + (e0 & 7)] = *(float4*)relu4;
    }
}

// ---------------- exact fp32 fixup of near-tie argmax decisions ----------------
// 256 threads = 32 s x 8 partials. Warp-shuffle reductions, 1 block barrier/iter.
__global__ void fixup_kernel(const float* __restrict__ x, const float* __restrict__ W0,
                             const float* __restrict__ b0) {
    __shared__ float zrow[NS];
    int cnt = g_candCount; if (cnt > CAND_CAP) cnt = CAND_CAP;
    const int t = threadIdx.x, s = t >> 3, p = t & 7;
    const int lane = t & 31;
    for (int i = blockIdx.x; i < cnt; i += gridDim.x) {
        int4 cd = g_cand[i];
        const float* xr = x + cd.x * ND;
        const float* wr = W0 + (size_t)s * (NH * ND) + cd.y * ND;
        float acc = 0.f;
        #pragma unroll 8
        for (int d = p * 32; d < p * 32 + 32; ++d) acc = fmaf(xr[d], wr[d], acc);
        float sum = acc;
        #pragma unroll
        for (int j = 1; j < 8; ++j) {
            float o = __shfl_sync(0xffffffffu, acc, (lane & 24) + j, 32);
            if (p == 0) sum += o;
        }
        if (p == 0) zrow[s] = sum + b0[s * NH + cd.y];
        __syncthreads();
        if (t < 32) {
            float zv = zrow[t];
            float m = __shfl_sync(0xffffffffu, zv, 0);
            int sm_ = 0;
            #pragma unroll
            for (int ss = 1; ss < NS; ++ss) {
                float o = __shfl_sync(0xffffffffu, zv, ss);
                if (o > m) { m = o; sm_ = ss; }
            }
            if (t == 0 && sm_ != cd.z) {
                atomicSub(&g_cnt[cd.y * NS + cd.z], 1);
                atomicAdd(&g_cnt[cd.y * NS + sm_], 1);
            }
        }
        __syncthreads();
    }
}

// ---------------- topKweights via histogram-weighted W0 ----------------
__global__ void topkw_kernel(const float* __restrict__ W0, float* __restrict__ out) {
    const int h = blockIdx.x;
    const int d = threadIdx.x;
    __shared__ float cs[NS];
    if (d < NS) cs[d] = (float)g_cnt[h * NS + d];
    __syncthreads();
    float mu = 0.f;
    #pragma unroll
    for (int k = 0; k < 16; ++k) mu += g_muPart[k][d];
    float acc = 0.f;
    #pragma unroll
    for (int s = 0; s < NS; ++s)
        acc = fmaf(cs[s], W0[(size_t)s * (NH * ND) + h * ND + d], acc);
    out[2 + NB * NC + h * ND + d] = acc * (1.f / (float)NB) + mu * (0.001f / (float)NB);
}

// ---------------- output head part 1: partial logits over a 128-h quarter ----
// grid (64 b-groups, 4 h-quarters) x 256 threads. 8 b-rows per block.
__global__ __launch_bounds__(256)
void outpart_kernel(const float* __restrict__ W1) {
    __shared__ float sx[8][NH / 4];    // 4 KB   (this quarter's h slice)
    __shared__ float w1s[32][129];     // 16.5 KB
    const int tid = threadIdx.x;
    const int lane = tid & 31, warp = tid >> 5;
    const int bBase = blockIdx.x * 8;
    const int hq = blockIdx.y;         // h-quarter
    const int hOff = hq * (NH / 4);

    {
        int i = tid;                   // float4 idx 0..255
        int r = i >> 5, col4 = i & 31;
        ((float4*)sx)[i] = ((const float4*)(g_hTop + (size_t)(bBase + r) * NH + hOff))[col4];
    }

    const int rg = warp >> 2;          // 0/1 -> rows rg*4..rg*4+3
    const int cq = warp & 3;
    const int c = cq * 32 + lane;
    float acc[4] = {0.f, 0.f, 0.f, 0.f};

    for (int ch = 0; ch < 4; ++ch) {
        __syncthreads();
        #pragma unroll
        for (int k = 0; k < 4; ++k) {
            int i = tid + k * 256;              // float4 idx 0..1023
            int c2 = i >> 3, col4 = i & 7;
            float4 v = ((const float4*)W1)[c2 * (NH / 4) + (hOff >> 2) + ch * 8 + col4];
            w1s[col4 * 4 + 0][c2] = v.x;
            w1s[col4 * 4 + 1][c2] = v.y;
            w1s[col4 * 4 + 2][c2] = v.z;
            w1s[col4 * 4 + 3][c2] = v.w;
        }
        __syncthreads();
        #pragma unroll
        for (int j4 = 0; j4 < 8; ++j4) {
            float w0v = w1s[j4 * 4 + 0][c];
            float w1v = w1s[j4 * 4 + 1][c];
            float w2v = w1s[j4 * 4 + 2][c];
            float w3v = w1s[j4 * 4 + 3][c];
            #pragma unroll
            for (int r = 0; r < 4; ++r) {
                float4 xv = *(const float4*)&sx[rg * 4 + r][ch * 32 + j4 * 4];
                acc[r] = fmaf(xv.x, w0v, acc[r]);
                acc[r] = fmaf(xv.y, w1v, acc[r]);
                acc[r] = fmaf(xv.z, w2v, acc[r]);
                acc[r] = fmaf(xv.w, w3v, acc[r]);
            }
        }
    }
    #pragma unroll
    for (int r = 0; r < 4; ++r)
        g_logPart[hq][(size_t)(bBase + rg * 4 + r) * NC + c] = acc[r];
}

// ---------------- output head part 2: combine + log_softmax ----------------
__global__ __launch_bounds__(256)
void softmax_kernel(const float* __restrict__ b1, const int* __restrict__ y,
                    float* __restrict__ out) {
    const int lane = threadIdx.x & 31, warp = threadIdx.x >> 5;
    const int b = blockIdx.x * 8 + warp;
    float v[4];
    #pragma unroll
    for (int k = 0; k < 4; ++k) {
        const int c = lane + k * 32;
        float s = b1[c];
        #pragma unroll
        for (int p = 0; p < 4; ++p) s += g_logPart[p][(size_t)b * NC + c];
        v[k] = s;
    }
    float m = v[0]; int am = lane;
    #pragma unroll
    for (int k = 1; k < 4; ++k)
        if (v[k] > m) { m = v[k]; am = lane + k * 32; }
    #pragma unroll
    for (int off = 16; off > 0; off >>= 1) {
        float om = __shfl_xor_sync(0xffffffffu, m, off);
        int oa = __shfl_xor_sync(0xffffffffu, am, off);
        if (om > m || (om == m && oa < am)) { m = om; am = oa; }
    }
    float ssum = 0.f;
    #pragma unroll
    for (int k = 0; k < 4; ++k) ssum += expf(v[k] - m);
    #pragma unroll
    for (int off = 16; off > 0; off >>= 1)
        ssum += __shfl_xor_sync(0xffffffffu, ssum, off);
    const float lse = logf(ssum);
    #pragma unroll
    for (int k = 0; k < 4; ++k)
        out[2 + (size_t)b * NC + lane + k * 32] = v[k] - m - lse;
    const int yb = y[b];
    if (lane == (yb & 31)) g_lossRow[b] = -(v[yb >> 5] - m - lse);
    if (lane == 0) g_corrRow[b] = (am == yb) ? 1.f : 0.f;
}

__global__ void finalize_kernel(float* out) {
    __shared__ float sl[NB], sc[NB];
    int t = threadIdx.x;
    sl[t] = g_lossRow[t];
    sc[t] = g_corrRow[t];
    __syncthreads();
    for (int off = NB / 2; off > 0; off >>= 1) {
        if (t < off) { sl[t] += sl[t + off]; sc[t] += sc[t + off]; }
        __syncthreads();
    }
    if (t == 0) { out[0] = sl[0] / (float)NB; out[1] = sc[0] / (float)NB; }
}

// ---------------- launcher ----------------
extern "C" void kernel_launch(void* const* d_in, const int* in_sizes, int n_in,
                              void* d_out, int out_size) {
    const float* x  = (const float*)d_in[0];
    const int*   y  = (const int*)d_in[1];
    const float* W0 = (const float*)d_in[2];
    const float* b0 = (const float*)d_in[3];
    const float* W1 = (const float*)d_in[4];
    const float* b1 = (const float*)d_in[5];
    float* out = (float*)d_out;

    static cudaStream_t s1;
    static cudaEvent_t eF, eX, eG, eO;
    static bool inited = false;
    if (!inited) {
        cudaStreamCreateWithFlags(&s1, cudaStreamNonBlocking);
        cudaEventCreateWithFlags(&eF, cudaEventDisableTiming);
        cudaEventCreateWithFlags(&eX, cudaEventDisableTiming);
        cudaEventCreateWithFlags(&eG, cudaEventDisableTiming);
        cudaEventCreateWithFlags(&eO, cudaEventDisableTiming);
        cudaFuncSetAttribute(gemm_mma_kernel,
                             cudaFuncAttributeMaxDynamicSharedMemorySize, 4 * STAGE_B);
        inited = true;
    }

    // fork side stream into the capture first, then launch on it
    cudaEventRecord(eF, 0);
    cudaStreamWaitEvent(s1, eF, 0);
    convx_kernel<<<128, 256, 0, s1>>>(x);
    cudaEventRecord(eX, s1);

    convw_kernel<<<4096, 256>>>(W0);
    cudaStreamWaitEvent(0, eX, 0);

    gemm_mma_kernel<<<dim3(64, 4), 256, 4 * STAGE_B>>>(b0);
    cudaEventRecord(eG, 0);

    // side stream: output head (depends only on g_hTop)
    cudaStreamWaitEvent(s1, eG, 0);
    outpart_kernel<<<dim3(64, 4), 256, 0, s1>>>(W1);
    softmax_kernel<<<64, 256, 0, s1>>>(b1, y, out);
    finalize_kernel<<<1, NB, 0, s1>>>(out);
    cudaEventRecord(eO, s1);

    // main stream: histogram correction + topKweights
    fixup_kernel<<<132, 256>>>(x, W0, b0);
    topkw_kernel<<<NH, ND>>>(W0, out);
    cudaStreamWaitEvent(0, eO, 0);
}